// round 6
// baseline (speedup 1.0000x reference)
#include <cuda_runtime.h>
#include <cuda_bf16.h>
#include <cstdint>

// ---------------------------------------------------------------------------
// Compile-time normalization constants K(l,m) baked in as immediates:
//   K = sqrt((2l+1)/(4pi) * (l-m)!/(l+m)!),   times sqrt(2) for m != 0
// ---------------------------------------------------------------------------
namespace {

constexpr double csqrt(double x) {
    double g = x > 1.0 ? x : 1.0;
    for (int i = 0; i < 100; i++) g = 0.5 * (g + x / g);
    return g;
}
constexpr double dfact(int n) {
    double r = 1.0;
    for (int i = 2; i <= n; i++) r *= (double)i;
    return r;
}
constexpr double PI_D = 3.14159265358979323846;

struct KTab { float c[8][8]; };

constexpr KTab mk_ktab() {
    KTab t{};
    for (int l = 0; l < 8; l++)
        for (int m = 0; m <= l; m++) {
            double K = csqrt((2.0 * l + 1.0) / (4.0 * PI_D)
                             * dfact(l - m) / dfact(l + m));
            if (m > 0) K *= csqrt(2.0);
            t.c[l][m] = (float)K;
        }
    return t;
}

__device__ constexpr KTab g_Kc = mk_ktab();

} // namespace

// ---------------------------------------------------------------------------
// Warp-autonomous l-outer pipeline. NO __syncthreads at all.
// Each warp owns 32 consecutive points; for region l its 32*w values form a
// CONTIGUOUS slice of the output, so the warp stages them in its own private
// smem chunk (lane stride w, odd => conflict-free) and lane 0 issues a
// per-warp cp.async.bulk after a __syncwarp. Warps drift apart in time,
// smoothing DRAM traffic; 28 copies/block in flight instead of 7.
//   region l chunk for warp wid: smem offset 128*(l*l-1) + wid*32*w
//   maps to out + N*l*l + (bs + wid*32)*w          (both 16B-aligned)
// l = 0 is the constant Y00 (direct coalesced store).
// ---------------------------------------------------------------------------
constexpr int TPB = 128;

__device__ __forceinline__ uint32_t smem_u32(const void* p) {
    uint32_t a;
    asm("{ .reg .u64 t; cvta.to.shared.u64 t, %1; cvt.u32.u64 %0, t; }"
        : "=r"(a) : "l"(p));
    return a;
}

__global__ __launch_bounds__(TPB)
void sph_harm_kernel(const float* __restrict__ cos_theta,
                     const float* __restrict__ phi,
                     float* __restrict__ out,
                     int N)
{
    __shared__ float smb[128 * 63];   // 31.5 KB, == output layout per block

    const int t    = threadIdx.x;
    const int wid  = t >> 5;
    const int lane = t & 31;
    const long long bs = (long long)blockIdx.x * TPB;
    const int n    = (int)bs + t;
    const int rows = (int)min((long long)TPB, (long long)N - bs);
    const bool full = (rows == TPB) && ((N & 3) == 0);

    const int nc = (n < N) ? n : (N - 1);

    const float x = cos_theta[nc];
    const float p = phi[nc];
    const float s = sqrtf(fmaxf(1.0f - x * x, 0.0f));

    float sp, cp;
    __sincosf(p, &sp, &cp);

    // l = 0 : Y00 is a constant.
    if (n < N) out[n] = g_Kc.c[0][0];

    // Recurrence state (fully unrolled -> registers).
    float Pp[8];    // P_{l-1}^m
    float Ppp[8];   // P_{l-2}^m
    float cmv[8], smv[8];
    Pp[0] = 1.0f;
    cmv[0] = 1.0f; smv[0] = 0.0f;

    #pragma unroll
    for (int l = 1; l <= 7; l++) {
        float Pl[8];
        #pragma unroll
        for (int m = 0; m <= l - 2; m++)
            Pl[m] = ((2.0f * l - 1.0f) * x * Pp[m]
                     - (float)(l + m - 1) * Ppp[m]) * (1.0f / (float)(l - m));
        Pl[l - 1] = (2.0f * l - 1.0f) * x * Pp[l - 1];
        Pl[l]     = -(2.0f * l - 1.0f) * s * Pp[l - 1];   // Condon-Shortley

        cmv[l] = cp * cmv[l - 1] - sp * smv[l - 1];
        smv[l] = sp * cmv[l - 1] + cp * smv[l - 1];

        const int w = 2 * l + 1;
        // warp-private chunk; lane stride w (odd) => conflict-free STS
        float* chunk = smb + 128 * (l * l - 1) + wid * 32 * w;
        {
            const int base = lane * w;
            chunk[base + l] = g_Kc.c[l][0] * Pl[0];
            #pragma unroll
            for (int m = 1; m <= l; m++) {
                const float kp = g_Kc.c[l][m] * Pl[m];
                chunk[base + (l - m)] = kp * smv[m];
                chunk[base + (l + m)] = kp * cmv[m];
            }
        }

        __syncwarp();

        if (full && lane == 0) {
            asm volatile("fence.proxy.async.shared::cta;" ::: "memory");
            const uint32_t src = smem_u32(chunk);
            float* dstp = out + (size_t)N * (size_t)(l * l)
                              + ((size_t)bs + (size_t)wid * 32) * (size_t)w;
            const uint32_t bytes = (uint32_t)(32 * w * 4);
            asm volatile(
                "cp.async.bulk.global.shared::cta.bulk_group [%0], [%1], %2;"
                :: "l"(dstp), "r"(src), "r"(bytes) : "memory");
            asm volatile("cp.async.bulk.commit_group;" ::: "memory");
        }

        #pragma unroll
        for (int m = 0; m <= l - 1; m++) Ppp[m] = Pp[m];
        #pragma unroll
        for (int m = 0; m <= l; m++)     Pp[m]  = Pl[m];
    }

    if (full) {
        // each warp's lane 0 drains its own copies; smem must stay alive
        if (lane == 0)
            asm volatile("cp.async.bulk.wait_group 0;" ::: "memory");
    } else {
        // tail / unaligned fallback (not hit for N = 2M)
        __syncthreads();
        #pragma unroll
        for (int l = 1; l <= 7; l++) {
            const int w = 2 * l + 1;
            // staged layout within block differs per-warp chunk; recompute
            // source index accordingly: element (pt, j) lives at
            // 128*(l*l-1) + (pt>>5)*32*w + (pt&31)*w + j  == same linear
            // order as output, so the simple copy below is still valid.
            const float* src = smb + 128 * (l * l - 1);
            float* dst = out + (size_t)N * (size_t)(l * l)
                             + (size_t)bs * (size_t)w;
            const int cnt = rows * w;
            for (int i = t; i < cnt; i += TPB)
                dst[i] = src[i];
        }
    }
}

extern "C" void kernel_launch(void* const* d_in, const int* in_sizes, int n_in,
                              void* d_out, int out_size)
{
    const float* cos_theta = (const float*)d_in[0];
    const float* phi       = (const float*)d_in[1];
    float* out             = (float*)d_out;
    const int N = in_sizes[0];

    const int blocks = (N + TPB - 1) / TPB;
    sph_harm_kernel<<<blocks, TPB>>>(cos_theta, phi, out, N);
}

// round 7
// speedup vs baseline: 1.2520x; 1.2520x over previous
#include <cuda_runtime.h>
#include <cuda_bf16.h>
#include <cstdint>

// ---------------------------------------------------------------------------
// Compile-time normalization constants K(l,m) baked in as immediates:
//   K = sqrt((2l+1)/(4pi) * (l-m)!/(l+m)!),   times sqrt(2) for m != 0
// ---------------------------------------------------------------------------
namespace {

constexpr double csqrt(double x) {
    double g = x > 1.0 ? x : 1.0;
    for (int i = 0; i < 100; i++) g = 0.5 * (g + x / g);
    return g;
}
constexpr double dfact(int n) {
    double r = 1.0;
    for (int i = 2; i <= n; i++) r *= (double)i;
    return r;
}
constexpr double PI_D = 3.14159265358979323846;

struct KTab { float c[8][8]; };

constexpr KTab mk_ktab() {
    KTab t{};
    for (int l = 0; l < 8; l++)
        for (int m = 0; m <= l; m++) {
            double K = csqrt((2.0 * l + 1.0) / (4.0 * PI_D)
                             * dfact(l - m) / dfact(l + m));
            if (m > 0) K *= csqrt(2.0);
            t.c[l][m] = (float)K;
        }
    return t;
}

__device__ constexpr KTab g_Kc = mk_ktab();

} // namespace

// ---------------------------------------------------------------------------
// Block-level l-outer pipeline, TPB = 256 (dynamic smem, 64.5 KB).
// SMEM staging buffer laid out IDENTICALLY to the output:
//   region l (l=1..7) at smem float offset 256*(l*l-1),
//   element (pt, j) at + pt*(2l+1) + j.   (lane stride w odd => conflict-free)
// Regions l=1..6: after a barrier, thread 0 issues one cp.async.bulk
//   shared->global per region (3..13 KB) that overlaps remaining compute.
// Region l=7 (largest): manual LDS.128/STG.128 copy by all threads — this
//   both writes the region and gives the six in-flight bulk copies time to
//   drain, making the final wait_group 0 ~free.
// l = 0 is the constant Y00 (direct coalesced store).
// ---------------------------------------------------------------------------
constexpr int TPB = 256;
constexpr int SMEM_BYTES = TPB * 63 * 4;   // 64512

__device__ __forceinline__ uint32_t smem_u32(const void* p) {
    uint32_t a;
    asm("{ .reg .u64 t; cvta.to.shared.u64 t, %1; cvt.u32.u64 %0, t; }"
        : "=r"(a) : "l"(p));
    return a;
}

__global__ __launch_bounds__(TPB)
void sph_harm_kernel(const float* __restrict__ cos_theta,
                     const float* __restrict__ phi,
                     float* __restrict__ out,
                     int N)
{
    extern __shared__ float smb[];   // TPB*63 floats, == output layout

    const int t  = threadIdx.x;
    const long long bs = (long long)blockIdx.x * TPB;
    const int n    = (int)bs + t;
    const int rows = (int)min((long long)TPB, (long long)N - bs);
    const bool full = (rows == TPB) && ((N & 3) == 0);

    const int nc = (n < N) ? n : (N - 1);

    const float x = cos_theta[nc];
    const float p = phi[nc];
    const float s = sqrtf(fmaxf(1.0f - x * x, 0.0f));

    float sp, cp;
    __sincosf(p, &sp, &cp);

    // l = 0 : Y00 is a constant.
    if (n < N) out[n] = g_Kc.c[0][0];

    // Recurrence state (fully unrolled -> registers).
    float Pp[8];    // P_{l-1}^m
    float Ppp[8];   // P_{l-2}^m
    float cmv[8], smv[8];
    Pp[0] = 1.0f;
    cmv[0] = 1.0f; smv[0] = 0.0f;

    #pragma unroll
    for (int l = 1; l <= 7; l++) {
        float Pl[8];
        #pragma unroll
        for (int m = 0; m <= l - 2; m++)
            Pl[m] = ((2.0f * l - 1.0f) * x * Pp[m]
                     - (float)(l + m - 1) * Ppp[m]) * (1.0f / (float)(l - m));
        Pl[l - 1] = (2.0f * l - 1.0f) * x * Pp[l - 1];
        Pl[l]     = -(2.0f * l - 1.0f) * s * Pp[l - 1];   // Condon-Shortley

        cmv[l] = cp * cmv[l - 1] - sp * smv[l - 1];
        smv[l] = sp * cmv[l - 1] + cp * smv[l - 1];

        // emit region l into smem (lane stride w odd -> conflict-free)
        {
            const int w    = 2 * l + 1;
            const int base = TPB * (l * l - 1) + t * w;
            smb[base + l] = g_Kc.c[l][0] * Pl[0];
            #pragma unroll
            for (int m = 1; m <= l; m++) {
                const float kp = g_Kc.c[l][m] * Pl[m];
                smb[base + (l - m)] = kp * smv[m];
                smb[base + (l + m)] = kp * cmv[m];
            }
        }

        if (l <= 6) {
            __syncthreads();
            if (full && t == 0) {
                asm volatile("fence.proxy.async.shared::cta;" ::: "memory");
                const int w = 2 * l + 1;
                const uint32_t src = smem_u32(smb + TPB * (l * l - 1));
                float* dstp = out + (size_t)N * (size_t)(l * l)
                                  + (size_t)bs * (size_t)w;
                const uint32_t bytes = (uint32_t)(TPB * w * 4);
                asm volatile(
                    "cp.async.bulk.global.shared::cta.bulk_group [%0], [%1], %2;"
                    :: "l"(dstp), "r"(src), "r"(bytes) : "memory");
                asm volatile("cp.async.bulk.commit_group;" ::: "memory");
            }
        }

        #pragma unroll
        for (int m = 0; m <= l - 1; m++) Ppp[m] = Pp[m];
        #pragma unroll
        for (int m = 0; m <= l; m++)     Pp[m]  = Pl[m];
    }

    __syncthreads();

    if (full) {
        // l=7 written manually (LDS.128 + STG.128, layout-identical copy);
        // overlaps the drain of the six outstanding bulk copies.
        {
            constexpr int l = 7, w = 15;
            const float4* src = (const float4*)(smb + TPB * (l * l - 1));
            float4* dst = (float4*)(out + (size_t)N * (size_t)(l * l)
                                        + (size_t)bs * (size_t)w);
            constexpr int cnt4 = (TPB * w) / 4;     // 960
            #pragma unroll
            for (int i = t; i < cnt4; i += TPB)
                dst[i] = src[i];
        }
        if (t == 0)
            asm volatile("cp.async.bulk.wait_group 0;" ::: "memory");
    } else {
        // tail / unaligned fallback (not hit for N = 2M)
        #pragma unroll
        for (int l = 1; l <= 7; l++) {
            const int w = 2 * l + 1;
            const float* src = smb + TPB * (l * l - 1);
            float* dst = out + (size_t)N * (size_t)(l * l)
                             + (size_t)bs * (size_t)w;
            const int cnt = rows * w;
            for (int i = t; i < cnt; i += TPB)
                dst[i] = src[i];
        }
    }
}

extern "C" void kernel_launch(void* const* d_in, const int* in_sizes, int n_in,
                              void* d_out, int out_size)
{
    const float* cos_theta = (const float*)d_in[0];
    const float* phi       = (const float*)d_in[1];
    float* out             = (float*)d_out;
    const int N = in_sizes[0];

    cudaFuncSetAttribute(sph_harm_kernel,
                         cudaFuncAttributeMaxDynamicSharedMemorySize,
                         SMEM_BYTES);

    const int blocks = (N + TPB - 1) / TPB;
    sph_harm_kernel<<<blocks, TPB, SMEM_BYTES>>>(cos_theta, phi, out, N);
}

// round 8
// speedup vs baseline: 1.2759x; 1.0191x over previous
#include <cuda_runtime.h>
#include <cuda_bf16.h>
#include <cstdint>

// ---------------------------------------------------------------------------
// Compile-time normalization constants K(l,m) baked in as immediates:
//   K = sqrt((2l+1)/(4pi) * (l-m)!/(l+m)!),   times sqrt(2) for m != 0
// ---------------------------------------------------------------------------
namespace {

constexpr double csqrt(double x) {
    double g = x > 1.0 ? x : 1.0;
    for (int i = 0; i < 100; i++) g = 0.5 * (g + x / g);
    return g;
}
constexpr double dfact(int n) {
    double r = 1.0;
    for (int i = 2; i <= n; i++) r *= (double)i;
    return r;
}
constexpr double PI_D = 3.14159265358979323846;

struct KTab { float c[8][8]; };

constexpr KTab mk_ktab() {
    KTab t{};
    for (int l = 0; l < 8; l++)
        for (int m = 0; m <= l; m++) {
            double K = csqrt((2.0 * l + 1.0) / (4.0 * PI_D)
                             * dfact(l - m) / dfact(l + m));
            if (m > 0) K *= csqrt(2.0);
            t.c[l][m] = (float)K;
        }
    return t;
}

__device__ constexpr KTab g_Kc = mk_ktab();

} // namespace

// ---------------------------------------------------------------------------
// l-outer pipeline with a 2-slot SMEM ring buffer (occupancy play).
// Slot size = largest region (w=15): 15*TPB floats. Region l is staged in
// slot (l&1) in output order (lane stride w odd => conflict-free STS), then
// ONE thread issues cp.async.bulk shared->global and does wait_group 1,
// guaranteeing the slot being reused next iteration (issued 2 regions ago)
// has drained. 30 KB smem + <=42 regs => 6 blocks/SM = 48 warps (vs 24).
// l = 0 is the constant Y00 (direct coalesced store).
// ---------------------------------------------------------------------------
constexpr int TPB = 256;
constexpr int SLOT_FLOATS = 15 * TPB;          // largest region (l=7)

__device__ __forceinline__ uint32_t smem_u32(const void* p) {
    uint32_t a;
    asm("{ .reg .u64 t; cvta.to.shared.u64 t, %1; cvt.u32.u64 %0, t; }"
        : "=r"(a) : "l"(p));
    return a;
}

__global__ __launch_bounds__(TPB, 6)
void sph_harm_kernel(const float* __restrict__ cos_theta,
                     const float* __restrict__ phi,
                     float* __restrict__ out,
                     int N)
{
    __shared__ float slot[2][SLOT_FLOATS];     // 30720 B

    const int t  = threadIdx.x;
    const long long bs = (long long)blockIdx.x * TPB;
    const int n    = (int)bs + t;
    const int rows = (int)min((long long)TPB, (long long)N - bs);
    const bool full = (rows == TPB) && ((N & 3) == 0);

    const int nc = (n < N) ? n : (N - 1);

    const float x = cos_theta[nc];
    const float p = phi[nc];
    const float s = sqrtf(fmaxf(1.0f - x * x, 0.0f));

    float sp, cp;
    __sincosf(p, &sp, &cp);

    // l = 0 : Y00 is a constant.
    if (n < N) out[n] = g_Kc.c[0][0];

    // Recurrence state (fully unrolled -> registers).
    float Pp[8];    // P_{l-1}^m
    float Ppp[8];   // P_{l-2}^m
    float cmv[8], smv[8];
    Pp[0] = 1.0f;
    cmv[0] = 1.0f; smv[0] = 0.0f;

    #pragma unroll
    for (int l = 1; l <= 7; l++) {
        float Pl[8];
        #pragma unroll
        for (int m = 0; m <= l - 2; m++)
            Pl[m] = ((2.0f * l - 1.0f) * x * Pp[m]
                     - (float)(l + m - 1) * Ppp[m]) * (1.0f / (float)(l - m));
        Pl[l - 1] = (2.0f * l - 1.0f) * x * Pp[l - 1];
        Pl[l]     = -(2.0f * l - 1.0f) * s * Pp[l - 1];   // Condon-Shortley

        cmv[l] = cp * cmv[l - 1] - sp * smv[l - 1];
        smv[l] = sp * cmv[l - 1] + cp * smv[l - 1];

        const int w = 2 * l + 1;
        float* buf = slot[l & 1];

        // stage region l (lane stride w odd -> conflict-free)
        {
            const int base = t * w;
            buf[base + l] = g_Kc.c[l][0] * Pl[0];
            #pragma unroll
            for (int m = 1; m <= l; m++) {
                const float kp = g_Kc.c[l][m] * Pl[m];
                buf[base + (l - m)] = kp * smv[m];
                buf[base + (l + m)] = kp * cmv[m];
            }
        }

        __syncthreads();                       // region staged

        if (full) {
            if (t == 0) {
                asm volatile("fence.proxy.async.shared::cta;" ::: "memory");
                const uint32_t src = smem_u32(buf);
                float* dstp = out + (size_t)N * (size_t)(l * l)
                                  + (size_t)bs * (size_t)w;
                const uint32_t bytes = (uint32_t)(TPB * w * 4);
                asm volatile(
                    "cp.async.bulk.global.shared::cta.bulk_group [%0], [%1], %2;"
                    :: "l"(dstp), "r"(src), "r"(bytes) : "memory");
                asm volatile("cp.async.bulk.commit_group;" ::: "memory");
                // allow 1 outstanding group: the copy issued for region l-1
                // (into the OTHER slot) may still fly; the one from l-2
                // (this slot) must have drained before we overwrite it.
                asm volatile("cp.async.bulk.wait_group 1;" ::: "memory");
            }
        } else {
            // tail / unaligned fallback (one block at N = 2M)
            float* dst = out + (size_t)N * (size_t)(l * l)
                             + (size_t)bs * (size_t)w;
            const int cnt = rows * w;
            for (int i = t; i < cnt; i += TPB)
                dst[i] = buf[i];
        }

        __syncthreads();                       // slot-reuse safety

        #pragma unroll
        for (int m = 0; m <= l - 1; m++) Ppp[m] = Pp[m];
        #pragma unroll
        for (int m = 0; m <= l; m++)     Pp[m]  = Pl[m];
    }

    if (full && t == 0)
        asm volatile("cp.async.bulk.wait_group 0;" ::: "memory");
}

extern "C" void kernel_launch(void* const* d_in, const int* in_sizes, int n_in,
                              void* d_out, int out_size)
{
    const float* cos_theta = (const float*)d_in[0];
    const float* phi       = (const float*)d_in[1];
    float* out             = (float*)d_out;
    const int N = in_sizes[0];

    const int blocks = (N + TPB - 1) / TPB;
    sph_harm_kernel<<<blocks, TPB>>>(cos_theta, phi, out, N);
}